// round 16
// baseline (speedup 1.0000x reference)
#include <cuda_runtime.h>
#include <cuda_fp16.h>
#include <cstdint>
#include <math.h>

// ---------------- problem constants ----------------
#define BB    64
#define MM    2048
#define NVOX  32768
#define FEAT  512
#define MARGIN 0.2f
#define BETA   0.8333333f

// voxel GEMM decomposition
#define MT    16          // m tiles of 128
#define KS    16          // split-K chunks
#define KCH   2048        // K per chunk
#define ITERS 32          // iterations of 64-K per chunk
// key-dist GEMM
#define KDS   8
#define KCH_KD 64
#define BN    128
#define BK    16

// ---------------- scratch (device globals; .bss zero-init, self-cleaning) --
__device__ float g_vwc [BB][MM];        // combined centered-dot (atomic-acc)
__device__ float g_wsqc [MM];
__device__ float g_wsumc[MM];
__device__ float g_vsqp [4][BB];
__device__ float g_vsump[4][BB];
__device__ float g_kdpc[BB][MM];        // combined key-dot (atomic-acc)
__device__ float g_asqc[BB];
__device__ float g_ksqc[MM];
__device__ float g_hpp[BB][MT];
__device__ float g_hnn[BB][MT];
__device__ int   g_ff [BB][MT];
__device__ int   g_done;                // epilogue completion counter (self-resetting)
__device__ int   g_prep_cnt[4];         // per-chunk prep completion (self-resetting)
// precomputed fp16 of (voxels - 0.5) — 4MB, L2-resident
__device__ __half g_bhi[BB * NVOX];

// ---------------- helpers ----------------
__device__ __forceinline__ uint32_t smem_u32(const void* p) {
    uint32_t a;
    asm("{ .reg .u64 t; cvta.to.shared.u64 t, %1; cvt.u32.u64 %0, t; }" : "=r"(a) : "l"(p));
    return a;
}
#define SWZ(off) ((off) ^ (((off) >> 3) & 0x70))

__device__ __forceinline__ void ldsm4(uint32_t* r, uint32_t addr) {
    asm volatile("ldmatrix.sync.aligned.m8n8.x4.shared.b16 {%0,%1,%2,%3}, [%4];"
        : "=r"(r[0]), "=r"(r[1]), "=r"(r[2]), "=r"(r[3]) : "r"(addr));
}
__device__ __forceinline__ void mma16816(float* d, const uint32_t* a, const uint32_t* b) {
    asm volatile("mma.sync.aligned.m16n8k16.row.col.f32.f16.f16.f32 "
        "{%0,%1,%2,%3}, {%4,%5,%6,%7}, {%8,%9}, {%0,%1,%2,%3};"
        : "+f"(d[0]), "+f"(d[1]), "+f"(d[2]), "+f"(d[3])
        : "r"(a[0]), "r"(a[1]), "r"(a[2]), "r"(a[3]), "r"(b[0]), "r"(b[1]));
}
__device__ __forceinline__ void pref_l2(const void* p) {
    asm volatile("prefetch.global.L2 [%0];" :: "l"(p));
}
__device__ __forceinline__ void cpa16(uint32_t dst, const void* src) {
    asm volatile("cp.async.cg.shared.global [%0], [%1], 16;" :: "r"(dst), "l"(src));
}
#define CPA_COMMIT() asm volatile("cp.async.commit_group;" ::: "memory")
#define CPA_WAIT2()  asm volatile("cp.async.wait_group 2;" ::: "memory")

// smem: A fp16 2 x 16KB at 0; B 4 x 8KB buffers at 32768 -> 64KB total
#define SM_B     32768
#define SM_TOTAL 65536

// ===========================================================================
// MEGA kernel (grid 640):
//   bid   0..255 -> prep: (vox-0.5)->fp16 g_bhi + exact vsq/vsum partials
//   bid 256..511 -> voxel GEMM tile; spin-waits on prep chunk; atomic-acc D
//   bid 512..639 -> key-dist GEMM; atomic-acc results
// ===========================================================================
__global__ void __launch_bounds__(256, 2)
k_mega(const float* __restrict__ vals, const float* __restrict__ vox,
       const float* __restrict__ anchor, const float* __restrict__ keys)
{
    extern __shared__ __align__(1024) char smem[];
    const uint32_t sb = smem_u32(smem);
    const int tid = threadIdx.x;

    if (blockIdx.x < 256) {
        // ======================= prep part =======================
        const int blk = blockIdx.x;
        const int r = blk >> 2, ch = blk & 3;
        const size_t base = (size_t)r * NVOX + (size_t)ch * (NVOX / 4);
        const float4* src = (const float4*)(vox + base);
        uint2* hi = (uint2*)(g_bhi + base);
        float sq = 0.f, sm = 0.f;
        for (int i = tid; i < NVOX / 16; i += 256) {
            float4 x = src[i];
            __half2 h01 = __float22half2_rn(make_float2(x.x - 0.5f, x.y - 0.5f));
            __half2 h23 = __float22half2_rn(make_float2(x.z - 0.5f, x.w - 0.5f));
            hi[i] = make_uint2(*(uint32_t*)&h01, *(uint32_t*)&h23);
            sq = fmaf(x.x, x.x, fmaf(x.y, x.y, fmaf(x.z, x.z, fmaf(x.w, x.w, sq))));
            sm += (x.x + x.y) + (x.z + x.w);
        }
        float* s1 = (float*)smem;
        float* s2 = s1 + 256;
        s1[tid] = sq; s2[tid] = sm;
        __syncthreads();
        for (int o = 128; o; o >>= 1) {
            if (tid < o) { s1[tid] += s1[tid + o]; s2[tid] += s2[tid + o]; }
            __syncthreads();
        }
        if (tid == 0) {
            g_vsqp[ch][r] = s1[0];
            g_vsump[ch][r] = s2[0];
            __threadfence();                      // publish g_bhi before count
            atomicAdd(&g_prep_cnt[ch], 1);
        }
        return;
    }

    if (blockIdx.x >= 512) {
        // =================== key-dist GEMM part ===================
        float* vs = (float*)smem;              // [BK][BB]
        float* ws = vs + BK * BB;              // [BK][BN]

        const int bid = blockIdx.x - 512;
        const int n0 = (bid & 15) * BN;
        const int kc = bid >> 4;
        const int k0 = kc * KCH_KD;
        const int tx = tid & 31, ty = tid >> 5;
        const int lrow = tid >> 2, lqd = (tid & 3) << 2;

        const float* vsrc  = anchor + (size_t)lrow * FEAT + k0 + lqd;
        const float* wsrc0 = keys + (size_t)(n0 + lrow) * FEAT + k0 + lqd;
        const float* wsrc1 = wsrc0 + (size_t)64 * FEAT;

        float4 rv = *(const float4*)vsrc;
        float4 rw0 = *(const float4*)wsrc0;
        float4 rw1 = *(const float4*)wsrc1;

        float acc[8][4];
#pragma unroll
        for (int i = 0; i < 8; i++)
#pragma unroll
            for (int j = 0; j < 4; j++) acc[i][j] = 0.f;

        float sqv = 0.f, sqw0 = 0.f, sqw1 = 0.f;

        constexpr int STEPS = KCH_KD / BK;
        for (int kt = 0; kt < STEPS; ++kt) {
            __syncthreads();
            vs[(lqd + 0) * BB + lrow] = rv.x;  vs[(lqd + 1) * BB + lrow] = rv.y;
            vs[(lqd + 2) * BB + lrow] = rv.z;  vs[(lqd + 3) * BB + lrow] = rv.w;
            ws[(lqd + 0) * BN + lrow] = rw0.x; ws[(lqd + 1) * BN + lrow] = rw0.y;
            ws[(lqd + 2) * BN + lrow] = rw0.z; ws[(lqd + 3) * BN + lrow] = rw0.w;
            ws[(lqd + 0) * BN + lrow + 64] = rw1.x; ws[(lqd + 1) * BN + lrow + 64] = rw1.y;
            ws[(lqd + 2) * BN + lrow + 64] = rw1.z; ws[(lqd + 3) * BN + lrow + 64] = rw1.w;
            sqv  += rv.x * rv.x + rv.y * rv.y + rv.z * rv.z + rv.w * rv.w;
            sqw0 += rw0.x * rw0.x + rw0.y * rw0.y + rw0.z * rw0.z + rw0.w * rw0.w;
            sqw1 += rw1.x * rw1.x + rw1.y * rw1.y + rw1.z * rw1.z + rw1.w * rw1.w;
            __syncthreads();
            if (kt + 1 < STEPS) {
                rv  = *(const float4*)(vsrc  + (kt + 1) * BK);
                rw0 = *(const float4*)(wsrc0 + (kt + 1) * BK);
                rw1 = *(const float4*)(wsrc1 + (kt + 1) * BK);
            }
#pragma unroll
            for (int kk = 0; kk < BK; ++kk) {
                float a[8], bv[4];
                *(float4*)&a[0] = *(const float4*)&vs[kk * BB + ty * 8];
                *(float4*)&a[4] = *(const float4*)&vs[kk * BB + ty * 8 + 4];
                *(float4*)&bv[0] = *(const float4*)&ws[kk * BN + tx * 4];
#pragma unroll
                for (int i = 0; i < 8; i++)
#pragma unroll
                    for (int j = 0; j < 4; j++)
                        acc[i][j] = fmaf(a[i], bv[j], acc[i][j]);
            }
        }
        const int b0 = ty * 8, nn = n0 + tx * 4;
#pragma unroll
        for (int i = 0; i < 8; i++)
#pragma unroll
            for (int j = 0; j < 4; j++)
                atomicAdd(&g_kdpc[b0 + i][nn + j], acc[i][j]);

        sqw0 += __shfl_xor_sync(0xffffffffu, sqw0, 1);
        sqw0 += __shfl_xor_sync(0xffffffffu, sqw0, 2);
        sqw1 += __shfl_xor_sync(0xffffffffu, sqw1, 1);
        sqw1 += __shfl_xor_sync(0xffffffffu, sqw1, 2);
        sqv  += __shfl_xor_sync(0xffffffffu, sqv, 1);
        sqv  += __shfl_xor_sync(0xffffffffu, sqv, 2);
        if ((tid & 3) == 0) {
            atomicAdd(&g_ksqc[n0 + lrow], sqw0);
            atomicAdd(&g_ksqc[n0 + 64 + lrow], sqw1);
            if ((bid & 15) == 0) atomicAdd(&g_asqc[lrow], sqv);
        }
        return;
    }

    // ======================= voxel GEMM part =======================
    const int bid = blockIdx.x - 256;
    const int wid = tid >> 5, lane = tid & 31;
    const int half = lane >> 4, lq = lane & 15;
    const int mt = bid & 15, kc = bid >> 4;
    const int m0 = mt * 128;
    const int k0 = kc * KCH;
    const int ch = kc >> 2;                   // prep chunk this CTA depends on

    // wait for prep chunk (all 64 rows of this K window converted)
    if (tid == 0) {
        while (((volatile int*)g_prep_cnt)[ch] < 64) __nanosleep(128);
    }
    __syncthreads();
    __threadfence();                          // acquire g_bhi writes

    const int wm = wid >> 1, wn = wid & 1;    // warp: 32m x 32n

    const int lrow8 = (lane & 7) + ((lane >> 3) & 1) * 8;
    const uint32_t lcol = (uint32_t)((lane >> 4) * 16);

    uint32_t aRB[2], aXM[2], bRB[2], bXM[2];
#pragma unroll
    for (int ms = 0; ms < 2; ms++) {
        int r = wm * 32 + ms * 16 + lrow8;
        aRB[ms] = sb + r * 128;
        aXM[ms] = (uint32_t)((r & 7) << 4);
    }
#pragma unroll
    for (int p = 0; p < 2; p++) {
        int r = wn * 32 + p * 16 + lrow8;
        bRB[p] = sb + SM_B + r * 128;
        bXM[p] = (uint32_t)((r & 7) << 4);
    }

    // B cp.async per-thread assignment (2 x 16B per buffer)
    const int brow = tid >> 2;
    const int bc0 = (tid & 3) * 2;
    const uint32_t bd0 = SWZ((uint32_t)(brow * 128 + bc0 * 16));
    const uint32_t bd1 = SWZ((uint32_t)(brow * 128 + (bc0 + 1) * 16));
    const char* bhsrc = (const char*)(g_bhi + (size_t)brow * NVOX + k0) + bc0 * 16;

    float acc[2][4][4];
#pragma unroll
    for (int i = 0; i < 2; i++)
#pragma unroll
        for (int j = 0; j < 4; j++)
#pragma unroll
            for (int c = 0; c < 4; c++) acc[i][j][c] = 0.f;

    float wsq[8], wsm[8];
#pragma unroll
    for (int s = 0; s < 8; s++) { wsq[s] = 0.f; wsm[s] = 0.f; }

    const float* aptr = vals + (size_t)m0 * NVOX + k0 + lq * 4;

    // ---- prologue ----
    float4 rva[8];
#pragma unroll
    for (int s = 0; s < 8; s++)
        rva[s] = *(const float4*)(aptr + (size_t)(wid * 16 + s * 2 + half) * NVOX);
#pragma unroll
    for (int d = 0; d < 3; d++) {
        uint32_t bb = sb + SM_B + (uint32_t)d * 8192u;
        cpa16(bb + bd0, bhsrc + d * 128);
        cpa16(bb + bd1, bhsrc + d * 128 + 16);
        CPA_COMMIT();
    }
#pragma unroll
    for (int s = 0; s < 8; s++)
        pref_l2(aptr + (size_t)(wid * 16 + s * 2 + half) * NVOX + 64);

    // convert A(0) -> buf0 (centered)
#pragma unroll
    for (int s = 0; s < 8; s++) {
        const int r = wid * 16 + s * 2 + half;
        float4 x = rva[s];
        __half2 h01 = __float22half2_rn(make_float2(x.x - 0.5f, x.y - 0.5f));
        __half2 h23 = __float22half2_rn(make_float2(x.z - 0.5f, x.w - 0.5f));
        wsq[s] = fmaf(x.x, x.x, fmaf(x.y, x.y, fmaf(x.z, x.z, fmaf(x.w, x.w, wsq[s]))));
        wsm[s] += (x.x + x.y) + (x.z + x.w);
        uint32_t off = SWZ((uint32_t)(r * 128 + lq * 8));
        *(uint2*)(smem + off) = make_uint2(*(uint32_t*)&h01, *(uint32_t*)&h23);
    }
    // load A(1)
#pragma unroll
    for (int s = 0; s < 8; s++)
        rva[s] = *(const float4*)(aptr + (size_t)(wid * 16 + s * 2 + half) * NVOX + 64);
#pragma unroll
    for (int s = 0; s < 8; s++)
        pref_l2(aptr + (size_t)(wid * 16 + s * 2 + half) * NVOX + 128);

    CPA_WAIT2();          // B(0) landed
    __syncthreads();

    // ---- main loop: MMA(it) interleaved with convert(it+1) ----
    for (int it = 0; it < ITERS - 1; ++it) {
        const uint32_t abo_m = (uint32_t)(it & 1) * 16384u;
        const uint32_t abo_c = (uint32_t)((it + 1) & 1) * 16384u;
        const uint32_t bbo   = (uint32_t)(it & 3) * 8192u;

        // issue B(it+3) into ring slot
        if (it + 3 < ITERS) {
            uint32_t bb = sb + SM_B + (uint32_t)((it + 3) & 3) * 8192u;
            const char* sh = bhsrc + (it + 3) * 128;
            cpa16(bb + bd0, sh);
            cpa16(bb + bd1, sh + 16);
        }
        CPA_COMMIT();

#pragma unroll
        for (int kk = 0; kk < 4; kk++) {
            const uint32_t col = (uint32_t)(kk * 32) + lcol;
            uint32_t aH[2][4];
#pragma unroll
            for (int ms = 0; ms < 2; ms++)
                ldsm4(aH[ms], aRB[ms] + abo_m + (col ^ aXM[ms]));
            uint32_t bH[2][4];
#pragma unroll
            for (int p = 0; p < 2; p++)
                ldsm4(bH[p], bRB[p] + bbo + (col ^ bXM[p]));
            // convert 2 A row-pairs for iter it+1
#pragma unroll
            for (int s = kk * 2; s < kk * 2 + 2; s++) {
                const int r = wid * 16 + s * 2 + half;
                float4 x = rva[s];
                __half2 h01 = __float22half2_rn(make_float2(x.x - 0.5f, x.y - 0.5f));
                __half2 h23 = __float22half2_rn(make_float2(x.z - 0.5f, x.w - 0.5f));
                wsq[s] = fmaf(x.x, x.x, fmaf(x.y, x.y,
                         fmaf(x.z, x.z, fmaf(x.w, x.w, wsq[s]))));
                wsm[s] += (x.x + x.y) + (x.z + x.w);
                uint32_t off = SWZ((uint32_t)(r * 128 + lq * 8));
                *(uint2*)(smem + abo_c + off) =
                    make_uint2(*(uint32_t*)&h01, *(uint32_t*)&h23);
            }
#pragma unroll
            for (int ms = 0; ms < 2; ms++)
#pragma unroll
                for (int j = 0; j < 4; j++) {
                    const int p = j >> 1, q = j & 1;
                    uint32_t bhf[2] = { bH[p][q], bH[p][q + 2] };
                    mma16816(acc[ms][j], aH[ms], bhf);
                }
        }

        // A loads for it+2 (batched); L2 prefetch it+3
        if (it + 2 < ITERS) {
            const int kb = (it + 2) * 64;
#pragma unroll
            for (int s = 0; s < 8; s++)
                rva[s] = *(const float4*)(aptr + (size_t)(wid * 16 + s * 2 + half) * NVOX + kb);
        }
        if (it + 3 < ITERS) {
            const int kb2 = (it + 3) * 64;
#pragma unroll
            for (int s = 0; s < 8; s++)
                pref_l2(aptr + (size_t)(wid * 16 + s * 2 + half) * NVOX + kb2);
        }

        CPA_WAIT2();          // B(it+1) landed
        __syncthreads();
    }

    // ---- final MMA (it = ITERS-1) ----
    {
        const uint32_t abo_m = (uint32_t)((ITERS - 1) & 1) * 16384u;
        const uint32_t bbo   = (uint32_t)((ITERS - 1) & 3) * 8192u;
#pragma unroll
        for (int kk = 0; kk < 4; kk++) {
            const uint32_t col = (uint32_t)(kk * 32) + lcol;
            uint32_t aH[2][4];
#pragma unroll
            for (int ms = 0; ms < 2; ms++)
                ldsm4(aH[ms], aRB[ms] + abo_m + (col ^ aXM[ms]));
            uint32_t bH[2][4];
#pragma unroll
            for (int p = 0; p < 2; p++)
                ldsm4(bH[p], bRB[p] + bbo + (col ^ bXM[p]));
#pragma unroll
            for (int ms = 0; ms < 2; ms++)
#pragma unroll
                for (int j = 0; j < 4; j++) {
                    const int p = j >> 1, q = j & 1;
                    uint32_t bhf[2] = { bH[p][q], bH[p][q + 2] };
                    mma16816(acc[ms][j], aH[ms], bhf);
                }
        }
    }

    // ---- wsq/wsum partials: shfl-reduce then atomic accumulate ----
#pragma unroll
    for (int s = 0; s < 8; s++) {
        float v = wsq[s], u = wsm[s];
#pragma unroll
        for (int o = 1; o < 16; o <<= 1) {
            v += __shfl_xor_sync(0xffffffffu, v, o);
            u += __shfl_xor_sync(0xffffffffu, u, o);
        }
        if (lq == 0) {
            atomicAdd(&g_wsqc [m0 + wid * 16 + s * 2 + half], v);
            atomicAdd(&g_wsumc[m0 + wid * 16 + s * 2 + half], u);
        }
    }

    // ---- stage D through smem as [b][m] fp32, atomic-accumulate ----
    __syncthreads();
    float* sd = (float*)smem;
#pragma unroll
    for (int ms = 0; ms < 2; ms++)
#pragma unroll
        for (int j = 0; j < 4; j++)
#pragma unroll
            for (int c = 0; c < 4; c++) {
                int ml = wm * 32 + ms * 16 + (lane >> 2) + ((c >> 1) << 3);
                int nn = wn * 32 + j * 8 + (lane & 3) * 2 + (c & 1);
                sd[nn * 128 + ml] = acc[ms][j][c];
            }
    __syncthreads();
#pragma unroll
    for (int i = 0; i < 8; i++) {
        int idx = tid + i * 256;
        int b = idx >> 5, mq = idx & 31;
        float4 v = ((const float4*)sd)[idx];
        float* dst = &g_vwc[b][m0 + mq * 4];
        atomicAdd(dst + 0, v.x);
        atomicAdd(dst + 1, v.y);
        atomicAdd(dst + 2, v.z);
        atomicAdd(dst + 3, v.w);
    }
}

// ===========================================================================
// Epilogue: grid (MT, BB) x 128 threads; 5 loads per thread (combined arrays),
// zeroes its own slices for the next graph replay; last block emits the loss
// and zeroes the shared small arrays + counters.
// ===========================================================================
__global__ void __launch_bounds__(128)
k_epilogue(float* __restrict__ out)
{
    const int mc = blockIdx.x, b = blockIdx.y;
    const int tid = threadIdx.x;
    const int m = mc * 128 + tid;
    __shared__ float s_hp[128], s_hn[128];
    __shared__ int   s_f[128];

    const float vsq  = g_vsqp [0][b] + g_vsqp [1][b] + g_vsqp [2][b] + g_vsqp [3][b];
    const float vsum = g_vsump[0][b] + g_vsump[1][b] + g_vsump[2][b] + g_vsump[3][b];

    float vwc = g_vwc[b][m];
    float wq  = g_wsqc[m];
    float wu  = g_wsumc[m];
    float kp  = g_kdpc[b][m];
    float kq  = g_ksqc[m];
    float asq = g_asqc[b];

    // zero the per-(b,m) slices this block alone reads (next replay)
    g_vwc[b][m] = 0.f;
    g_kdpc[b][m] = 0.f;

    const float an = fmaxf(sqrtf(asq), 1e-8f);

    // de-center: v·w = Σ(v-½)(w-½) + ½Σv + ½Σw − N/4
    float vw = vwc + 0.5f * (vsum + wu) - 8192.0f;
    float sv = 1.0f - (vsq + wq - 2.0f * vw) * (1.0f / (float)NVOX);
    float kn = fmaxf(sqrtf(kq), 1e-8f);
    float kd = 1.0f - kp / (an * kn);

    float hp = -1e30f, hn = 1e30f;
    int fl = 0;
    if (sv > BETA) { fl |= 1; hp = kd; }
    if (sv < BETA) { fl |= 2; hn = kd; }

    s_hp[tid] = hp; s_hn[tid] = hn; s_f[tid] = fl;
    __syncthreads();
    for (int o = 64; o; o >>= 1) {
        if (tid < o) {
            s_hp[tid] = fmaxf(s_hp[tid], s_hp[tid + o]);
            s_hn[tid] = fminf(s_hn[tid], s_hn[tid + o]);
            s_f[tid] |= s_f[tid + o];
        }
        __syncthreads();
    }
    __shared__ int s_last;
    if (tid == 0) {
        g_hpp[b][mc] = s_hp[0];
        g_hnn[b][mc] = s_hn[0];
        g_ff [b][mc] = s_f[0];
        __threadfence();
        int old = atomicAdd(&g_done, 1);
        s_last = (old == MT * BB - 1) ? 1 : 0;
    }
    __syncthreads();
    if (!s_last) return;

    // ---- final reduction (single surviving block) ----
    __shared__ float sl[BB], sc[BB];
    if (tid < BB) {
        float fhp = -1e30f, fhn = 1e30f;
        int ff = 0;
#pragma unroll
        for (int c = 0; c < MT; c++) {
            fhp = fmaxf(fhp, g_hpp[tid][c]);
            fhn = fminf(fhn, g_hnn[tid][c]);
            ff |= g_ff[tid][c];
        }
        bool v = (ff == 3);
        sl[tid] = v ? fmaxf(fhp - fhn + MARGIN, 0.f) : 0.f;
        sc[tid] = v ? 1.f : 0.f;
    }
    __syncthreads();
    for (int o = 32; o; o >>= 1) {
        if (tid < o) { sl[tid] += sl[tid + o]; sc[tid] += sc[tid + o]; }
        __syncthreads();
    }
    if (tid == 0) {
        out[0] = (sc[0] > 0.f) ? (sl[0] / fmaxf(sc[0], 1.f)) : 0.f;
        g_done = 0;               // reset for next graph replay
        g_prep_cnt[0] = 0; g_prep_cnt[1] = 0;
        g_prep_cnt[2] = 0; g_prep_cnt[3] = 0;
    }
    // zero shared small arrays for next replay (all 128 threads)
    for (int i = tid; i < MM; i += 128) {
        g_wsqc[i] = 0.f;
        g_wsumc[i] = 0.f;
        g_ksqc[i] = 0.f;
    }
    if (tid < BB) g_asqc[tid] = 0.f;
}

// ===========================================================================
extern "C" void kernel_launch(void* const* d_in, const int* in_sizes, int n_in,
                              void* d_out, int out_size)
{
    (void)in_sizes; (void)n_in; (void)out_size;
    const float* anchor = (const float*)d_in[0];   // (64, 512)
    const float* voxels = (const float*)d_in[1];   // (64, 32^3)
    const float* keys   = (const float*)d_in[2];   // (2048, 512)
    const float* vals   = (const float*)d_in[3];   // (2048, 32^3)
    float* out = (float*)d_out;

    cudaFuncSetAttribute(k_mega, cudaFuncAttributeMaxDynamicSharedMemorySize, SM_TOTAL);

    k_mega<<<640, 256, SM_TOTAL>>>(vals, voxels, anchor, keys);  // #1
    k_epilogue<<<dim3(MT, BB), 128>>>(out);                      // #2
}

// round 17
// speedup vs baseline: 1.1204x; 1.1204x over previous
#include <cuda_runtime.h>
#include <cuda_fp16.h>
#include <cstdint>
#include <math.h>

// ---------------- problem constants ----------------
#define BB    64
#define MM    2048
#define NVOX  32768
#define FEAT  512
#define MARGIN 0.2f
#define BETA   0.8333333f

// voxel GEMM decomposition
#define MT    16          // m tiles of 128
#define KS    16          // split-K chunks
#define KCH   2048        // K per chunk
#define ITERS 32          // iterations of 64-K per chunk
// key-dist GEMM
#define KDS   8
#define KCH_KD 64
#define BN    128
#define BK    16

// ---------------- scratch (device globals) ----------------
__device__ float g_vw  [KS][BB][MM];    // centered-dot partials
__device__ float g_wsq [KS][MM];
__device__ float g_wsum[KS][MM];
__device__ float g_vsqp [4][BB];
__device__ float g_vsump[4][BB];
__device__ float g_kdp[KDS][BB][MM];
__device__ float g_asq[KDS][BB];
__device__ float g_ksq[KDS][MM];
__device__ float g_hpp[BB][MT];
__device__ float g_hnn[BB][MT];
__device__ int   g_ff [BB][MT];
__device__ int   g_done;                // epilogue completion counter (self-resetting)
__device__ int   g_prep_cnt[4];         // per-chunk prep completion (self-resetting)
// precomputed fp16 of (voxels - 0.5) — 4MB, L2-resident
__device__ __half g_bhi[BB * NVOX];

// ---------------- helpers ----------------
__device__ __forceinline__ uint32_t smem_u32(const void* p) {
    uint32_t a;
    asm("{ .reg .u64 t; cvta.to.shared.u64 t, %1; cvt.u32.u64 %0, t; }" : "=r"(a) : "l"(p));
    return a;
}
#define SWZ(off) ((off) ^ (((off) >> 3) & 0x70))

__device__ __forceinline__ void ldsm4(uint32_t* r, uint32_t addr) {
    asm volatile("ldmatrix.sync.aligned.m8n8.x4.shared.b16 {%0,%1,%2,%3}, [%4];"
        : "=r"(r[0]), "=r"(r[1]), "=r"(r[2]), "=r"(r[3]) : "r"(addr));
}
__device__ __forceinline__ void mma16816(float* d, const uint32_t* a, const uint32_t* b) {
    asm volatile("mma.sync.aligned.m16n8k16.row.col.f32.f16.f16.f32 "
        "{%0,%1,%2,%3}, {%4,%5,%6,%7}, {%8,%9}, {%0,%1,%2,%3};"
        : "+f"(d[0]), "+f"(d[1]), "+f"(d[2]), "+f"(d[3])
        : "r"(a[0]), "r"(a[1]), "r"(a[2]), "r"(a[3]), "r"(b[0]), "r"(b[1]));
}
__device__ __forceinline__ void pref_l2(const void* p) {
    asm volatile("prefetch.global.L2 [%0];" :: "l"(p));
}
// streaming (evict-first) float4 load — A has zero reuse, keep it out of L2
__device__ __forceinline__ float4 ldcs4(const float* p) {
    return __ldcs((const float4*)p);
}
__device__ __forceinline__ void cpa16(uint32_t dst, const void* src) {
    asm volatile("cp.async.cg.shared.global [%0], [%1], 16;" :: "r"(dst), "l"(src));
}
#define CPA_COMMIT() asm volatile("cp.async.commit_group;" ::: "memory")
#define CPA_WAIT2()  asm volatile("cp.async.wait_group 2;" ::: "memory")

// smem: A fp16 2 x 16KB at 0; B 4 x 8KB buffers at 32768 -> 64KB total
#define SM_B     32768
#define SM_TOTAL 65536

// ===========================================================================
// MEGA kernel (grid 640):
//   bid   0..255 -> prep: (vox-0.5)->fp16 g_bhi + exact vsq/vsum partials
//   bid 256..511 -> voxel GEMM tile (mt = b&15, kc = b>>4); spin-waits on
//                   g_prep_cnt[kc>>2]==64 before first B cp.async
//   bid 512..639 -> key-dist GEMM (independent; fills idle occupancy slots)
// ===========================================================================
__global__ void __launch_bounds__(256, 2)
k_mega(const float* __restrict__ vals, const float* __restrict__ vox,
       const float* __restrict__ anchor, const float* __restrict__ keys)
{
    extern __shared__ __align__(1024) char smem[];
    const uint32_t sb = smem_u32(smem);
    const int tid = threadIdx.x;

    if (blockIdx.x < 256) {
        // ======================= prep part =======================
        const int blk = blockIdx.x;
        const int r = blk >> 2, ch = blk & 3;
        const size_t base = (size_t)r * NVOX + (size_t)ch * (NVOX / 4);
        const float4* src = (const float4*)(vox + base);
        uint2* hi = (uint2*)(g_bhi + base);
        float sq = 0.f, sm = 0.f;
        for (int i = tid; i < NVOX / 16; i += 256) {
            float4 x = src[i];
            __half2 h01 = __float22half2_rn(make_float2(x.x - 0.5f, x.y - 0.5f));
            __half2 h23 = __float22half2_rn(make_float2(x.z - 0.5f, x.w - 0.5f));
            hi[i] = make_uint2(*(uint32_t*)&h01, *(uint32_t*)&h23);
            sq = fmaf(x.x, x.x, fmaf(x.y, x.y, fmaf(x.z, x.z, fmaf(x.w, x.w, sq))));
            sm += (x.x + x.y) + (x.z + x.w);
        }
        float* s1 = (float*)smem;
        float* s2 = s1 + 256;
        s1[tid] = sq; s2[tid] = sm;
        __syncthreads();
        for (int o = 128; o; o >>= 1) {
            if (tid < o) { s1[tid] += s1[tid + o]; s2[tid] += s2[tid + o]; }
            __syncthreads();
        }
        if (tid == 0) {
            g_vsqp[ch][r] = s1[0];
            g_vsump[ch][r] = s2[0];
            __threadfence();                      // publish g_bhi before count
            atomicAdd(&g_prep_cnt[ch], 1);
        }
        return;
    }

    if (blockIdx.x >= 512) {
        // =================== key-dist GEMM part ===================
        float* vs = (float*)smem;              // [BK][BB]
        float* ws = vs + BK * BB;              // [BK][BN]

        const int bid = blockIdx.x - 512;
        const int n0 = (bid & 15) * BN;
        const int kc = bid >> 4;
        const int k0 = kc * KCH_KD;
        const int tx = tid & 31, ty = tid >> 5;
        const int lrow = tid >> 2, lqd = (tid & 3) << 2;

        const float* vsrc  = anchor + (size_t)lrow * FEAT + k0 + lqd;
        const float* wsrc0 = keys + (size_t)(n0 + lrow) * FEAT + k0 + lqd;
        const float* wsrc1 = wsrc0 + (size_t)64 * FEAT;

        float4 rv = *(const float4*)vsrc;
        float4 rw0 = *(const float4*)wsrc0;
        float4 rw1 = *(const float4*)wsrc1;

        float acc[8][4];
#pragma unroll
        for (int i = 0; i < 8; i++)
#pragma unroll
            for (int j = 0; j < 4; j++) acc[i][j] = 0.f;

        float sqv = 0.f, sqw0 = 0.f, sqw1 = 0.f;

        constexpr int STEPS = KCH_KD / BK;
        for (int kt = 0; kt < STEPS; ++kt) {
            __syncthreads();
            vs[(lqd + 0) * BB + lrow] = rv.x;  vs[(lqd + 1) * BB + lrow] = rv.y;
            vs[(lqd + 2) * BB + lrow] = rv.z;  vs[(lqd + 3) * BB + lrow] = rv.w;
            ws[(lqd + 0) * BN + lrow] = rw0.x; ws[(lqd + 1) * BN + lrow] = rw0.y;
            ws[(lqd + 2) * BN + lrow] = rw0.z; ws[(lqd + 3) * BN + lrow] = rw0.w;
            ws[(lqd + 0) * BN + lrow + 64] = rw1.x; ws[(lqd + 1) * BN + lrow + 64] = rw1.y;
            ws[(lqd + 2) * BN + lrow + 64] = rw1.z; ws[(lqd + 3) * BN + lrow + 64] = rw1.w;
            sqv  += rv.x * rv.x + rv.y * rv.y + rv.z * rv.z + rv.w * rv.w;
            sqw0 += rw0.x * rw0.x + rw0.y * rw0.y + rw0.z * rw0.z + rw0.w * rw0.w;
            sqw1 += rw1.x * rw1.x + rw1.y * rw1.y + rw1.z * rw1.z + rw1.w * rw1.w;
            __syncthreads();
            if (kt + 1 < STEPS) {
                rv  = *(const float4*)(vsrc  + (kt + 1) * BK);
                rw0 = *(const float4*)(wsrc0 + (kt + 1) * BK);
                rw1 = *(const float4*)(wsrc1 + (kt + 1) * BK);
            }
#pragma unroll
            for (int kk = 0; kk < BK; ++kk) {
                float a[8], bv[4];
                *(float4*)&a[0] = *(const float4*)&vs[kk * BB + ty * 8];
                *(float4*)&a[4] = *(const float4*)&vs[kk * BB + ty * 8 + 4];
                *(float4*)&bv[0] = *(const float4*)&ws[kk * BN + tx * 4];
#pragma unroll
                for (int i = 0; i < 8; i++)
#pragma unroll
                    for (int j = 0; j < 4; j++)
                        acc[i][j] = fmaf(a[i], bv[j], acc[i][j]);
            }
        }
        const int b0 = ty * 8, nn = n0 + tx * 4;
#pragma unroll
        for (int i = 0; i < 8; i++)
            *(float4*)&g_kdp[kc][b0 + i][nn] =
                make_float4(acc[i][0], acc[i][1], acc[i][2], acc[i][3]);

        sqw0 += __shfl_xor_sync(0xffffffffu, sqw0, 1);
        sqw0 += __shfl_xor_sync(0xffffffffu, sqw0, 2);
        sqw1 += __shfl_xor_sync(0xffffffffu, sqw1, 1);
        sqw1 += __shfl_xor_sync(0xffffffffu, sqw1, 2);
        sqv  += __shfl_xor_sync(0xffffffffu, sqv, 1);
        sqv  += __shfl_xor_sync(0xffffffffu, sqv, 2);
        if ((tid & 3) == 0) {
            g_ksq[kc][n0 + lrow]      = sqw0;
            g_ksq[kc][n0 + 64 + lrow] = sqw1;
            if ((bid & 15) == 0) g_asq[kc][lrow] = sqv;
        }
        return;
    }

    // ======================= voxel GEMM part =======================
    const int bid = blockIdx.x - 256;
    const int wid = tid >> 5, lane = tid & 31;
    const int half = lane >> 4, lq = lane & 15;
    const int mt = bid & 15, kc = bid >> 4;
    const int m0 = mt * 128;
    const int k0 = kc * KCH;
    const int ch = kc >> 2;                   // prep chunk this CTA depends on

    // wait for prep chunk (all 64 rows of this K window converted)
    if (tid == 0) {
        while (((volatile int*)g_prep_cnt)[ch] < 64) __nanosleep(128);
    }
    __syncthreads();
    __threadfence();                          // acquire g_bhi writes

    const int wm = wid >> 1, wn = wid & 1;    // warp: 32m x 32n

    const int lrow8 = (lane & 7) + ((lane >> 3) & 1) * 8;
    const uint32_t lcol = (uint32_t)((lane >> 4) * 16);

    uint32_t aRB[2], aXM[2], bRB[2], bXM[2];
#pragma unroll
    for (int ms = 0; ms < 2; ms++) {
        int r = wm * 32 + ms * 16 + lrow8;
        aRB[ms] = sb + r * 128;
        aXM[ms] = (uint32_t)((r & 7) << 4);
    }
#pragma unroll
    for (int p = 0; p < 2; p++) {
        int r = wn * 32 + p * 16 + lrow8;
        bRB[p] = sb + SM_B + r * 128;
        bXM[p] = (uint32_t)((r & 7) << 4);
    }

    // B cp.async per-thread assignment (2 x 16B per buffer)
    const int brow = tid >> 2;
    const int bc0 = (tid & 3) * 2;
    const uint32_t bd0 = SWZ((uint32_t)(brow * 128 + bc0 * 16));
    const uint32_t bd1 = SWZ((uint32_t)(brow * 128 + (bc0 + 1) * 16));
    const char* bhsrc = (const char*)(g_bhi + (size_t)brow * NVOX + k0) + bc0 * 16;

    float acc[2][4][4];
#pragma unroll
    for (int i = 0; i < 2; i++)
#pragma unroll
        for (int j = 0; j < 4; j++)
#pragma unroll
            for (int c = 0; c < 4; c++) acc[i][j][c] = 0.f;

    float wsq[8], wsm[8];
#pragma unroll
    for (int s = 0; s < 8; s++) { wsq[s] = 0.f; wsm[s] = 0.f; }

    const float* aptr = vals + (size_t)m0 * NVOX + k0 + lq * 4;

    // ---- prologue ----
    float4 rva[8];
#pragma unroll
    for (int s = 0; s < 8; s++)
        rva[s] = ldcs4(aptr + (size_t)(wid * 16 + s * 2 + half) * NVOX);
#pragma unroll
    for (int d = 0; d < 3; d++) {
        uint32_t bb = sb + SM_B + (uint32_t)d * 8192u;
        cpa16(bb + bd0, bhsrc + d * 128);
        cpa16(bb + bd1, bhsrc + d * 128 + 16);
        CPA_COMMIT();
    }
#pragma unroll
    for (int s = 0; s < 8; s++)
        pref_l2(aptr + (size_t)(wid * 16 + s * 2 + half) * NVOX + 64);

    // convert A(0) -> buf0 (centered)
#pragma unroll
    for (int s = 0; s < 8; s++) {
        const int r = wid * 16 + s * 2 + half;
        float4 x = rva[s];
        __half2 h01 = __float22half2_rn(make_float2(x.x - 0.5f, x.y - 0.5f));
        __half2 h23 = __float22half2_rn(make_float2(x.z - 0.5f, x.w - 0.5f));
        wsq[s] = fmaf(x.x, x.x, fmaf(x.y, x.y, fmaf(x.z, x.z, fmaf(x.w, x.w, wsq[s]))));
        wsm[s] += (x.x + x.y) + (x.z + x.w);
        uint32_t off = SWZ((uint32_t)(r * 128 + lq * 8));
        *(uint2*)(smem + off) = make_uint2(*(uint32_t*)&h01, *(uint32_t*)&h23);
    }
    // load A(1)
#pragma unroll
    for (int s = 0; s < 8; s++)
        rva[s] = ldcs4(aptr + (size_t)(wid * 16 + s * 2 + half) * NVOX + 64);
#pragma unroll
    for (int s = 0; s < 8; s++)
        pref_l2(aptr + (size_t)(wid * 16 + s * 2 + half) * NVOX + 128);

    CPA_WAIT2();          // B(0) landed
    __syncthreads();

    // ---- main loop: MMA(it) interleaved with convert(it+1) ----
    for (int it = 0; it < ITERS - 1; ++it) {
        const uint32_t abo_m = (uint32_t)(it & 1) * 16384u;
        const uint32_t abo_c = (uint32_t)((it + 1) & 1) * 16384u;
        const uint32_t bbo   = (uint32_t)(it & 3) * 8192u;

        // issue B(it+3) into ring slot
        if (it + 3 < ITERS) {
            uint32_t bb = sb + SM_B + (uint32_t)((it + 3) & 3) * 8192u;
            const char* sh = bhsrc + (it + 3) * 128;
            cpa16(bb + bd0, sh);
            cpa16(bb + bd1, sh + 16);
        }
        CPA_COMMIT();

#pragma unroll
        for (int kk = 0; kk < 4; kk++) {
            const uint32_t col = (uint32_t)(kk * 32) + lcol;
            uint32_t aH[2][4];
#pragma unroll
            for (int ms = 0; ms < 2; ms++)
                ldsm4(aH[ms], aRB[ms] + abo_m + (col ^ aXM[ms]));
            uint32_t bH[2][4];
#pragma unroll
            for (int p = 0; p < 2; p++)
                ldsm4(bH[p], bRB[p] + bbo + (col ^ bXM[p]));
            // convert 2 A row-pairs for iter it+1
#pragma unroll
            for (int s = kk * 2; s < kk * 2 + 2; s++) {
                const int r = wid * 16 + s * 2 + half;
                float4 x = rva[s];
                __half2 h01 = __float22half2_rn(make_float2(x.x - 0.5f, x.y - 0.5f));
                __half2 h23 = __float22half2_rn(make_float2(x.z - 0.5f, x.w - 0.5f));
                wsq[s] = fmaf(x.x, x.x, fmaf(x.y, x.y,
                         fmaf(x.z, x.z, fmaf(x.w, x.w, wsq[s]))));
                wsm[s] += (x.x + x.y) + (x.z + x.w);
                uint32_t off = SWZ((uint32_t)(r * 128 + lq * 8));
                *(uint2*)(smem + abo_c + off) =
                    make_uint2(*(uint32_t*)&h01, *(uint32_t*)&h23);
            }
#pragma unroll
            for (int ms = 0; ms < 2; ms++)
#pragma unroll
                for (int j = 0; j < 4; j++) {
                    const int p = j >> 1, q = j & 1;
                    uint32_t bhf[2] = { bH[p][q], bH[p][q + 2] };
                    mma16816(acc[ms][j], aH[ms], bhf);
                }
        }

        // A loads for it+2 (batched); L2 prefetch it+3
        if (it + 2 < ITERS) {
            const int kb = (it + 2) * 64;
#pragma unroll
            for (int s = 0; s < 8; s++)
                rva[s] = ldcs4(aptr + (size_t)(wid * 16 + s * 2 + half) * NVOX + kb);
        }
        if (it + 3 < ITERS) {
            const int kb2 = (it + 3) * 64;
#pragma unroll
            for (int s = 0; s < 8; s++)
                pref_l2(aptr + (size_t)(wid * 16 + s * 2 + half) * NVOX + kb2);
        }

        CPA_WAIT2();          // B(it+1) landed
        __syncthreads();
    }

    // ---- final MMA (it = ITERS-1) ----
    {
        const uint32_t abo_m = (uint32_t)((ITERS - 1) & 1) * 16384u;
        const uint32_t bbo   = (uint32_t)((ITERS - 1) & 3) * 8192u;
#pragma unroll
        for (int kk = 0; kk < 4; kk++) {
            const uint32_t col = (uint32_t)(kk * 32) + lcol;
            uint32_t aH[2][4];
#pragma unroll
            for (int ms = 0; ms < 2; ms++)
                ldsm4(aH[ms], aRB[ms] + abo_m + (col ^ aXM[ms]));
            uint32_t bH[2][4];
#pragma unroll
            for (int p = 0; p < 2; p++)
                ldsm4(bH[p], bRB[p] + bbo + (col ^ bXM[p]));
#pragma unroll
            for (int ms = 0; ms < 2; ms++)
#pragma unroll
                for (int j = 0; j < 4; j++) {
                    const int p = j >> 1, q = j & 1;
                    uint32_t bhf[2] = { bH[p][q], bH[p][q + 2] };
                    mma16816(acc[ms][j], aH[ms], bhf);
                }
        }
    }

    // ---- wsq/wsum partials (reduce 16 lanes sharing a row) ----
#pragma unroll
    for (int s = 0; s < 8; s++) {
        float v = wsq[s], u = wsm[s];
#pragma unroll
        for (int o = 1; o < 16; o <<= 1) {
            v += __shfl_xor_sync(0xffffffffu, v, o);
            u += __shfl_xor_sync(0xffffffffu, u, o);
        }
        if (lq == 0) {
            g_wsq [kc][m0 + wid * 16 + s * 2 + half] = v;
            g_wsum[kc][m0 + wid * 16 + s * 2 + half] = u;
        }
    }

    // ---- stage D through smem as [b][m] fp32, coalesced store ----
    __syncthreads();
    float* sd = (float*)smem;
#pragma unroll
    for (int ms = 0; ms < 2; ms++)
#pragma unroll
        for (int j = 0; j < 4; j++)
#pragma unroll
            for (int c = 0; c < 4; c++) {
                int ml = wm * 32 + ms * 16 + (lane >> 2) + ((c >> 1) << 3);
                int nn = wn * 32 + j * 8 + (lane & 3) * 2 + (c & 1);
                sd[nn * 128 + ml] = acc[ms][j][c];
            }
    __syncthreads();
#pragma unroll
    for (int i = 0; i < 8; i++) {
        int idx = tid + i * 256;
        int b = idx >> 5, mq = idx & 31;
        *(float4*)&g_vw[kc][b][m0 + mq * 4] = ((const float4*)sd)[idx];
    }
}

// ===========================================================================
// Epilogue: grid (MT, BB) = 1024 blocks x 256 threads. Threads 0..127 handle
// split-K halves s=0..7 (KDS 0..3) for m = mc*128+tid; threads 128..255 handle
// s=8..15 (KDS 4..7). Halves combined via smem; last block emits the loss.
// ===========================================================================
__global__ void __launch_bounds__(256)
k_epilogue(float* __restrict__ out)
{
    const int mc = blockIdx.x, b = blockIdx.y;
    const int tid = threadIdx.x;
    const int lm = tid & 127;
    const int hs = tid >> 7;                 // 0 or 1: which split-K half
    const int m = mc * 128 + lm;

    float vw = 0.f, wq = 0.f, wu = 0.f;
#pragma unroll
    for (int s = hs * 8; s < hs * 8 + 8; s++) {
        vw += g_vw  [s][b][m];
        wq += g_wsq [s][m];
        wu += g_wsum[s][m];
    }
    float kp = 0.f, kq = 0.f;
#pragma unroll
    for (int s = hs * 4; s < hs * 4 + 4; s++) {
        kp += g_kdp[s][b][m];
        kq += g_ksq[s][m];
    }

    __shared__ float s_vw[256], s_wq[256], s_wu[256], s_kp[256], s_kq[256];
    s_vw[tid] = vw; s_wq[tid] = wq; s_wu[tid] = wu;
    s_kp[tid] = kp; s_kq[tid] = kq;
    __syncthreads();

    __shared__ float s_hp[128], s_hn[128];
    __shared__ int   s_f[128];

    if (tid < 128) {
        // combine halves (s=0..7 first, then s=8..15 — fixed order)
        vw = s_vw[tid] + s_vw[tid + 128];
        wq = s_wq[tid] + s_wq[tid + 128];
        wu = s_wu[tid] + s_wu[tid + 128];
        kp = s_kp[tid] + s_kp[tid + 128];
        kq = s_kq[tid] + s_kq[tid + 128];

        const float vsq  = g_vsqp [0][b] + g_vsqp [1][b] + g_vsqp [2][b] + g_vsqp [3][b];
        const float vsum = g_vsump[0][b] + g_vsump[1][b] + g_vsump[2][b] + g_vsump[3][b];
        float asq = 0.f;
#pragma unroll
        for (int s = 0; s < KDS; s++) asq += g_asq[s][b];
        const float an = fmaxf(sqrtf(asq), 1e-8f);

        // de-center: v·w = Σ(v-½)(w-½) + ½Σv + ½Σw − N/4
        float vwf = vw + 0.5f * (vsum + wu) - 8192.0f;
        float sv = 1.0f - (vsq + wq - 2.0f * vwf) * (1.0f / (float)NVOX);
        float kn = fmaxf(sqrtf(kq), 1e-8f);
        float kd = 1.0f - kp / (an * kn);

        float hp = -1e30f, hn = 1e30f;
        int fl = 0;
        if (sv > BETA) { fl |= 1; hp = kd; }
        if (sv < BETA) { fl |= 2; hn = kd; }

        s_hp[tid] = hp; s_hn[tid] = hn; s_f[tid] = fl;
    }
    __syncthreads();
    for (int o = 64; o; o >>= 1) {
        if (tid < o) {
            s_hp[tid] = fmaxf(s_hp[tid], s_hp[tid + o]);
            s_hn[tid] = fminf(s_hn[tid], s_hn[tid + o]);
            s_f[tid] |= s_f[tid + o];
        }
        __syncthreads();
    }

    __shared__ int s_last;
    if (tid == 0) {
        g_hpp[b][mc] = s_hp[0];
        g_hnn[b][mc] = s_hn[0];
        g_ff [b][mc] = s_f[0];
        __threadfence();
        int old = atomicAdd(&g_done, 1);
        s_last = (old == MT * BB - 1) ? 1 : 0;
    }
    __syncthreads();
    if (!s_last) return;

    // ---- final reduction (single surviving block) ----
    __shared__ float sl[BB], sc[BB];
    if (tid < BB) {
        float fhp = -1e30f, fhn = 1e30f;
        int ff = 0;
#pragma unroll
        for (int c = 0; c < MT; c++) {
            fhp = fmaxf(fhp, g_hpp[tid][c]);
            fhn = fminf(fhn, g_hnn[tid][c]);
            ff |= g_ff[tid][c];
        }
        bool v = (ff == 3);
        sl[tid] = v ? fmaxf(fhp - fhn + MARGIN, 0.f) : 0.f;
        sc[tid] = v ? 1.f : 0.f;
    }
    __syncthreads();
    for (int o = 32; o; o >>= 1) {
        if (tid < o) { sl[tid] += sl[tid + o]; sc[tid] += sc[tid + o]; }
        __syncthreads();
    }
    if (tid == 0) {
        out[0] = (sc[0] > 0.f) ? (sl[0] / fmaxf(sc[0], 1.f)) : 0.f;
        g_done = 0;               // reset for next graph replay
        g_prep_cnt[0] = 0; g_prep_cnt[1] = 0;
        g_prep_cnt[2] = 0; g_prep_cnt[3] = 0;
    }
}

// ===========================================================================
extern "C" void kernel_launch(void* const* d_in, const int* in_sizes, int n_in,
                              void* d_out, int out_size)
{
    (void)in_sizes; (void)n_in; (void)out_size;
    const float* anchor = (const float*)d_in[0];   // (64, 512)
    const float* voxels = (const float*)d_in[1];   // (64, 32^3)
    const float* keys   = (const float*)d_in[2];   // (2048, 512)
    const float* vals   = (const float*)d_in[3];   // (2048, 32^3)
    float* out = (float*)d_out;

    cudaFuncSetAttribute(k_mega, cudaFuncAttributeMaxDynamicSharedMemorySize, SM_TOTAL);

    k_mega<<<640, 256, SM_TOTAL>>>(vals, voxels, anchor, keys);  // #1
    k_epilogue<<<dim3(MT, BB), 256>>>(out);                      // #2
}